// round 1
// baseline (speedup 1.0000x reference)
#include <cuda_runtime.h>
#include <cuda_bf16.h>
#include <cstdint>

#define BATCH   16
#define SEQ     512
#define DIM     128
#define HID     1024
#define NLAYER  6
#define NHEAD   16
#define HEADDIM 64
#define AHID    2730
#define NTOK    8192              // BATCH*SEQ
#define RSCALE  0.4082482904638630f   // 1/sqrt(6)
#define RMSEPS  1e-6f

// ---------------------------------------------------------------------------
// Scratch (static device globals; allocation-free per harness rules)
// ---------------------------------------------------------------------------
__device__ float g_h   [(size_t)NTOK * HID];
__device__ float g_g   [(size_t)NTOK * HID];
__device__ float g_q   [(size_t)NTOK * HID];
__device__ float g_k   [(size_t)NTOK * HID];
__device__ float g_v   [(size_t)NTOK * HID];
__device__ float g_o   [(size_t)NTOK * HID];
__device__ float g_sc  [(size_t)BATCH * NHEAD * SEQ * SEQ];   // 268 MB
__device__ float g_ff1 [(size_t)NTOK * AHID];
__device__ float g_ff3 [(size_t)NTOK * AHID];
__device__ float g_cos [SEQ * 32];
__device__ float g_sin [SEQ * 32];

// ---------------------------------------------------------------------------
// bf16 split GEMM:  C = beta?C:0 + alpha * (A @ B(+T) + bias)
// A fp32 row-major MxK (lda), B fp32 KxN (ldb) or transB: NxK (ldb).
// Split each operand into hi+lo bf16; acc += Ah*Bh + Ah*Bl + Al*Bh (fp32 acc).
// Batched via blockIdx.z with 2-level stride decomposition (z = zq*bdiv+zr).
// ---------------------------------------------------------------------------
#define MMA16816(d, A0,A1,A2,A3, B0,B1)                                      \
  asm volatile("mma.sync.aligned.m16n8k16.row.col.f32.bf16.bf16.f32 "        \
               "{%0,%1,%2,%3}, {%4,%5,%6,%7}, {%8,%9}, {%0,%1,%2,%3};"       \
               : "+f"(d[0]), "+f"(d[1]), "+f"(d[2]), "+f"(d[3])              \
               : "r"(A0), "r"(A1), "r"(A2), "r"(A3), "r"(B0), "r"(B1))

__global__ void __launch_bounds__(256, 1)
gemm_bf16split_kernel(const float* __restrict__ A, const float* __restrict__ B,
                      float* __restrict__ C, const float* __restrict__ bias,
                      int M, int N, int K, int lda, int ldb, int ldc,
                      int transB, float alpha, int accum,
                      int bdiv, long long sA1, long long sA2,
                      long long sB1, long long sB2,
                      long long sC1, long long sC2)
{
    // smem tiles: 128 rows x 32 k, padded to 40 bf16/row (bank-conflict-free frags)
    __shared__ __nv_bfloat16 sAh[128*40], sAl[128*40], sBh[128*40], sBl[128*40];

    const int tid  = threadIdx.x;
    const int lane = tid & 31, warp = tid >> 5;
    const int wm = warp >> 1, wn = warp & 1;       // 4x2 warp grid (32x64 per warp)
    const int g  = lane >> 2, t4 = lane & 3;

    const int z  = blockIdx.z;
    const int zq = z / bdiv, zr = z - zq * bdiv;
    const float* Ab = A + zq * sA1 + (long long)zr * sA2;
    const float* Bb = B + zq * sB1 + (long long)zr * sB2;
    float*       Cb = C + zq * sC1 + (long long)zr * sC2;

    const int m0 = blockIdx.y * 128, n0 = blockIdx.x * 128;

    float acc[2][8][4];
    #pragma unroll
    for (int i = 0; i < 2; i++)
        #pragma unroll
        for (int j = 0; j < 8; j++)
            #pragma unroll
            for (int e = 0; e < 4; e++) acc[i][j][e] = 0.f;

    for (int kt = 0; kt < K; kt += 32) {
        __syncthreads();
        // ---- load A tile (row-major, coalesced 128B per warp-row) ----
        #pragma unroll
        for (int i = 0; i < 16; i++) {
            int idx = i * 256 + tid;
            int r = idx >> 5, c = idx & 31;
            int gm = m0 + r, gk = kt + c;
            float v = 0.f;
            if (gm < M && gk < K) v = Ab[(long long)gm * lda + gk];
            __nv_bfloat16 hi = __float2bfloat16(v);
            sAh[r*40 + c] = hi;
            sAl[r*40 + c] = __float2bfloat16(v - __bfloat162float(hi));
        }
        // ---- load B tile into [n][k] layout ----
        #pragma unroll
        for (int i = 0; i < 16; i++) {
            int idx = i * 256 + tid;
            int n, c;
            float v = 0.f;
            if (!transB) {
                c = idx >> 7; n = idx & 127;          // coalesced along n
                int gk = kt + c, gn = n0 + n;
                if (gk < K && gn < N) v = Bb[(long long)gk * ldb + gn];
            } else {
                n = idx >> 5; c = idx & 31;           // coalesced along k
                int gn = n0 + n, gk = kt + c;
                if (gn < N && gk < K) v = Bb[(long long)gn * ldb + gk];
            }
            __nv_bfloat16 hi = __float2bfloat16(v);
            sBh[n*40 + c] = hi;
            sBl[n*40 + c] = __float2bfloat16(v - __bfloat162float(hi));
        }
        __syncthreads();

        // ---- 2 k-steps of m16n8k16 ----
        #pragma unroll
        for (int ks = 0; ks < 2; ks++) {
            uint32_t ah[2][4], al[2][4], bh[8][2], bl[8][2];
            #pragma unroll
            for (int mt = 0; mt < 2; mt++) {
                int r = wm*32 + mt*16 + g;
                int c = ks*16 + 2*t4;
                ah[mt][0] = *(const uint32_t*)&sAh[ r   *40 + c    ];
                ah[mt][1] = *(const uint32_t*)&sAh[(r+8)*40 + c    ];
                ah[mt][2] = *(const uint32_t*)&sAh[ r   *40 + c + 8];
                ah[mt][3] = *(const uint32_t*)&sAh[(r+8)*40 + c + 8];
                al[mt][0] = *(const uint32_t*)&sAl[ r   *40 + c    ];
                al[mt][1] = *(const uint32_t*)&sAl[(r+8)*40 + c    ];
                al[mt][2] = *(const uint32_t*)&sAl[ r   *40 + c + 8];
                al[mt][3] = *(const uint32_t*)&sAl[(r+8)*40 + c + 8];
            }
            #pragma unroll
            for (int nt = 0; nt < 8; nt++) {
                int n = wn*64 + nt*8 + g;
                int c = ks*16 + 2*t4;
                bh[nt][0] = *(const uint32_t*)&sBh[n*40 + c    ];
                bh[nt][1] = *(const uint32_t*)&sBh[n*40 + c + 8];
                bl[nt][0] = *(const uint32_t*)&sBl[n*40 + c    ];
                bl[nt][1] = *(const uint32_t*)&sBl[n*40 + c + 8];
            }
            #pragma unroll
            for (int mt = 0; mt < 2; mt++)
                #pragma unroll
                for (int nt = 0; nt < 8; nt++) {
                    MMA16816(acc[mt][nt], ah[mt][0],ah[mt][1],ah[mt][2],ah[mt][3], bh[nt][0],bh[nt][1]);
                    MMA16816(acc[mt][nt], ah[mt][0],ah[mt][1],ah[mt][2],ah[mt][3], bl[nt][0],bl[nt][1]);
                    MMA16816(acc[mt][nt], al[mt][0],al[mt][1],al[mt][2],al[mt][3], bh[nt][0],bh[nt][1]);
                }
        }
    }

    // ---- epilogue: bias, alpha, optional residual accumulate ----
    #pragma unroll
    for (int mt = 0; mt < 2; mt++)
        #pragma unroll
        for (int nt = 0; nt < 8; nt++) {
            int r = m0 + wm*32 + mt*16 + g;
            int c = n0 + wn*64 + nt*8 + 2*t4;
            #pragma unroll
            for (int e = 0; e < 4; e++) {
                int rr = r + (e >> 1) * 8;
                int cc = c + (e & 1);
                if (rr < M && cc < N) {
                    float v = acc[mt][nt][e];
                    if (bias) v += bias[cc];
                    v *= alpha;
                    long long o = (long long)rr * ldc + cc;
                    if (accum) v += Cb[o];
                    Cb[o] = v;
                }
            }
        }
}

// ---------------------------------------------------------------------------
// RMSNorm: one row (H=1024) per block of 256
// ---------------------------------------------------------------------------
__global__ void rmsnorm_kernel(const float* __restrict__ x,
                               const float* __restrict__ w,
                               float* __restrict__ out)
{
    long long row = blockIdx.x;
    const float* xr = x + row * HID;
    float*       orw = out + row * HID;
    float s = 0.f;
    #pragma unroll
    for (int c = threadIdx.x; c < HID; c += 256) { float v = xr[c]; s += v * v; }
    #pragma unroll
    for (int o = 16; o; o >>= 1) s += __shfl_xor_sync(0xffffffffu, s, o);
    __shared__ float red[8];
    int warp = threadIdx.x >> 5, lane = threadIdx.x & 31;
    if (lane == 0) red[warp] = s;
    __syncthreads();
    float tot = red[0]+red[1]+red[2]+red[3]+red[4]+red[5]+red[6]+red[7];
    float inv = rsqrtf(tot * (1.0f / HID) + RMSEPS);
    #pragma unroll
    for (int c = threadIdx.x; c < HID; c += 256)
        orw[c] = xr[c] * inv * w[c];
}

// ---------------------------------------------------------------------------
// RoPE cache + apply
// ---------------------------------------------------------------------------
__global__ void rope_cache_kernel()
{
    int i = blockIdx.x * blockDim.x + threadIdx.x;
    if (i >= SEQ * 32) return;
    int s = i >> 5, j = i & 31;
    float invf = expf(-(float)j * (1.0f / 32.0f) * logf(10000.0f));
    float a = (float)s * invf;
    g_cos[i] = cosf(a);
    g_sin[i] = sinf(a);
}

__global__ void rope_apply_kernel()
{
    int i = blockIdx.x * blockDim.x + threadIdx.x;   // NTOK * NHEAD * 32
    if (i >= NTOK * NHEAD * 32) return;
    int m   = i >> 9;
    int rem = i & 511;
    int h = rem >> 5, j = rem & 31;
    int s = m & (SEQ - 1);
    float c  = g_cos[s*32 + j];
    float sn = g_sin[s*32 + j];
    long long base = (long long)m * HID + h * HEADDIM + j;
    float q1 = g_q[base], q2 = g_q[base + 32];
    g_q[base]      = q1 * c - q2 * sn;
    g_q[base + 32] = q2 * c + q1 * sn;
    float k1 = g_k[base], k2 = g_k[base + 32];
    g_k[base]      = k1 * c - k2 * sn;
    g_k[base + 32] = k2 * c + k1 * sn;
}

// ---------------------------------------------------------------------------
// Softmax over rows of 512 (one warp per row, 8 rows per block)
// ---------------------------------------------------------------------------
__global__ void softmax_kernel(float* __restrict__ sc)
{
    long long row = (long long)blockIdx.x * 8 + (threadIdx.x >> 5);
    int lane = threadIdx.x & 31;
    float* p = sc + row * SEQ;
    float e[16];
    float mx = -3.4e38f;
    #pragma unroll
    for (int i = 0; i < 16; i++) { e[i] = p[lane + i*32]; mx = fmaxf(mx, e[i]); }
    #pragma unroll
    for (int o = 16; o; o >>= 1) mx = fmaxf(mx, __shfl_xor_sync(0xffffffffu, mx, o));
    float sum = 0.f;
    #pragma unroll
    for (int i = 0; i < 16; i++) { e[i] = __expf(e[i] - mx); sum += e[i]; }
    #pragma unroll
    for (int o = 16; o; o >>= 1) sum += __shfl_xor_sync(0xffffffffu, sum, o);
    float r = 1.0f / sum;
    #pragma unroll
    for (int i = 0; i < 16; i++) p[lane + i*32] = e[i] * r;
}

// ---------------------------------------------------------------------------
// SwiGLU elementwise: ff1 <- silu(ff1) * ff3
// ---------------------------------------------------------------------------
__global__ void swiglu_kernel(long long n)
{
    long long i = (long long)blockIdx.x * blockDim.x + threadIdx.x;
    if (i >= n) return;
    float a = g_ff1[i], b = g_ff3[i];
    float sig = 1.0f / (1.0f + __expf(-a));
    g_ff1[i] = a * sig * b;
}

// ---------------------------------------------------------------------------
// Host-side launch plumbing
// ---------------------------------------------------------------------------
static void gemm(const float* A, const float* B, float* C, const float* bias,
                 int M, int N, int K, int lda, int ldb, int ldc,
                 int transB, float alpha, int accum,
                 int batches = 1, int bdiv = 1,
                 long long sA1 = 0, long long sA2 = 0,
                 long long sB1 = 0, long long sB2 = 0,
                 long long sC1 = 0, long long sC2 = 0)
{
    dim3 grid((N + 127) / 128, (M + 127) / 128, batches);
    gemm_bf16split_kernel<<<grid, 256>>>(A, B, C, bias, M, N, K, lda, ldb, ldc,
                                         transB, alpha, accum, bdiv,
                                         sA1, sA2, sB1, sB2, sC1, sC2);
}

extern "C" void kernel_launch(void* const* d_in, const int* in_sizes, int n_in,
                              void* d_out, int out_size)
{
    const float* x       = (const float*)d_in[0];
    const float* in_w    = (const float*)d_in[1];
    const float* in_b    = (const float*)d_in[2];
    const float* norm1_w = (const float*)d_in[3];
    const float* norm2_w = (const float*)d_in[4];
    const float* wq      = (const float*)d_in[5];
    const float* bq      = (const float*)d_in[6];
    const float* wk      = (const float*)d_in[7];
    const float* bk      = (const float*)d_in[8];
    const float* wv      = (const float*)d_in[9];
    const float* bv      = (const float*)d_in[10];
    const float* wo      = (const float*)d_in[11];
    const float* bo      = (const float*)d_in[12];
    const float* w1      = (const float*)d_in[13];
    const float* b1      = (const float*)d_in[14];
    const float* w3      = (const float*)d_in[15];
    const float* b3      = (const float*)d_in[16];
    const float* w2      = (const float*)d_in[17];
    const float* b2      = (const float*)d_in[18];
    const float* onorm_w = (const float*)d_in[19];
    const float* out_w   = (const float*)d_in[20];
    const float* out_b   = (const float*)d_in[21];
    float* out = (float*)d_out;

    float *ph, *pg, *pq, *pk, *pv, *po, *ps, *pf1, *pf3;
    cudaGetSymbolAddress((void**)&ph,  g_h);
    cudaGetSymbolAddress((void**)&pg,  g_g);
    cudaGetSymbolAddress((void**)&pq,  g_q);
    cudaGetSymbolAddress((void**)&pk,  g_k);
    cudaGetSymbolAddress((void**)&pv,  g_v);
    cudaGetSymbolAddress((void**)&po,  g_o);
    cudaGetSymbolAddress((void**)&ps,  g_sc);
    cudaGetSymbolAddress((void**)&pf1, g_ff1);
    cudaGetSymbolAddress((void**)&pf3, g_ff3);

    rope_cache_kernel<<<(SEQ*32 + 255) / 256, 256>>>();

    // h = x @ in_w + in_b
    gemm(x, in_w, ph, in_b, NTOK, HID, DIM, DIM, HID, HID, 0, 1.0f, 0);

    for (int l = 0; l < NLAYER; l++) {
        const long long hh = (long long)HID * HID;
        const long long ha = (long long)HID * AHID;

        // g = rmsnorm(h) * norm1_w
        rmsnorm_kernel<<<NTOK, 256>>>(ph, norm1_w + (long long)l*HID, pg);

        // q,k,v = g @ w{q,k,v} + b
        gemm(pg, wq + l*hh, pq, bq + (long long)l*HID, NTOK, HID, HID, HID, HID, HID, 0, 1.0f, 0);
        gemm(pg, wk + l*hh, pk, bk + (long long)l*HID, NTOK, HID, HID, HID, HID, HID, 0, 1.0f, 0);
        gemm(pg, wv + l*hh, pv, bv + (long long)l*HID, NTOK, HID, HID, HID, HID, HID, 0, 1.0f, 0);

        rope_apply_kernel<<<(NTOK*NHEAD*32 + 255) / 256, 256>>>();

        // scores[b,h] = scale * Q Kt   (batched over z = b*16+h)
        gemm(pq, pk, ps, nullptr, SEQ, SEQ, HEADDIM, HID, HID, SEQ,
             /*transB*/1, 0.125f, 0,
             BATCH*NHEAD, NHEAD,
             (long long)SEQ*HID, HEADDIM,
             (long long)SEQ*HID, HEADDIM,
             (long long)NHEAD*SEQ*SEQ, (long long)SEQ*SEQ);

        softmax_kernel<<<BATCH*NHEAD*SEQ/8, 256>>>(ps);

        // o[b,h] = P @ V   (written back to [token][H] layout)
        gemm(ps, pv, po, nullptr, SEQ, HEADDIM, SEQ, SEQ, HID, HID,
             /*transB*/0, 1.0f, 0,
             BATCH*NHEAD, NHEAD,
             (long long)NHEAD*SEQ*SEQ, (long long)SEQ*SEQ,
             (long long)SEQ*HID, HEADDIM,
             (long long)SEQ*HID, HEADDIM);

        // h += (o @ wo + bo) * RS
        gemm(po, wo + l*hh, ph, bo + (long long)l*HID, NTOK, HID, HID, HID, HID, HID, 0, RSCALE, 1);

        // g = rmsnorm(h) * norm2_w
        rmsnorm_kernel<<<NTOK, 256>>>(ph, norm2_w + (long long)l*HID, pg);

        // ff1 = g@w1+b1 ; ff3 = g@w3+b3 ; ff1 = silu(ff1)*ff3
        gemm(pg, w1 + l*ha, pf1, b1 + (long long)l*AHID, NTOK, AHID, HID, HID, AHID, AHID, 0, 1.0f, 0);
        gemm(pg, w3 + l*ha, pf3, b3 + (long long)l*AHID, NTOK, AHID, HID, HID, AHID, AHID, 0, 1.0f, 0);
        {
            long long n = (long long)NTOK * AHID;
            swiglu_kernel<<<(unsigned)((n + 255) / 256), 256>>>(n);
        }
        // h += (ff1 @ w2 + b2) * RS
        gemm(pf1, w2 + (long long)l*AHID*HID, ph, b2 + (long long)l*HID,
             NTOK, HID, AHID, AHID, HID, HID, 0, RSCALE, 1);
    }

    // out = rmsnorm(h, onorm) @ out_w + out_b
    rmsnorm_kernel<<<NTOK, 256>>>(ph, onorm_w, pg);
    gemm(pg, out_w, out, out_b, NTOK, DIM, HID, HID, DIM, DIM, 0, 1.0f, 0);
}

// round 2
// speedup vs baseline: 1.5875x; 1.5875x over previous
#include <cuda_runtime.h>
#include <cuda_bf16.h>
#include <cstdint>

#define BATCH   16
#define SEQ     512
#define DIM     128
#define HID     1024
#define NLAYER  6
#define NHEAD   16
#define HEADDIM 64
#define AHID    2730
#define APAD    2736              // 16B-aligned row pitch for AHID arrays
#define NTOK    8192
#define RSCALE  0.4082482904638630f
#define RMSEPS  1e-6f

// GEMM tiling
#define BK 32
#define NSTAGE 3
#define SPITCH 40                          // bf16 elems per smem row (80B, conflict-free)
#define TILE_ELEMS (128*SPITCH)            // 5120 bf16 per plane tile
#define STAGE_ELEMS (4*TILE_ELEMS)         // Ah,Al,Bh,Bl
#define SMEM_BYTES (NSTAGE*STAGE_ELEMS*2)  // 122880

// ---------------------------------------------------------------------------
// Device scratch (allocation-free)
// ---------------------------------------------------------------------------
// weight planes, [N][K] (pre-transposed), hi & lo
__device__ __nv_bfloat16 g_winh[131072],            g_winl[131072];
__device__ __nv_bfloat16 g_wqh [6*1048576],         g_wql [6*1048576];
__device__ __nv_bfloat16 g_wkh [6*1048576],         g_wkl [6*1048576];
__device__ __nv_bfloat16 g_wvh [6*1048576],         g_wvl [6*1048576];
__device__ __nv_bfloat16 g_woh [6*1048576],         g_wol [6*1048576];
__device__ __nv_bfloat16 g_w1h [6*2795520],         g_w1l [6*2795520];   // [A][H]
__device__ __nv_bfloat16 g_w3h [6*2795520],         g_w3l [6*2795520];   // [A][H]
__device__ __nv_bfloat16 g_w2h [6*1024*APAD],       g_w2l [6*1024*APAD]; // [H][APAD]
__device__ __nv_bfloat16 g_outwh[131072],           g_outwl[131072];
// activation planes
__device__ __nv_bfloat16 g_xh [1048576],            g_xl [1048576];
__device__ __nv_bfloat16 g_gh [8388608],            g_gl [8388608];
__device__ __nv_bfloat16 g_qh [8388608],            g_ql [8388608];
__device__ __nv_bfloat16 g_kh [8388608],            g_kl [8388608];
__device__ __nv_bfloat16 g_vth[8388608],            g_vtl[8388608];      // [HID][NTOK]
__device__ __nv_bfloat16 g_oh [8388608],            g_ol [8388608];
__device__ __nv_bfloat16 g_ph [67108864],           g_pl [67108864];
__device__ __nv_bfloat16 g_ffh[(size_t)NTOK*APAD],  g_ffl[(size_t)NTOK*APAD];
// fp32 scratch
__device__ float g_h  [8388608];
__device__ float g_qf [8388608];
__device__ float g_kf [8388608];
__device__ float g_vf [8388608];
__device__ float g_sc [67108864];
__device__ float g_ff1[(size_t)NTOK*AHID];
__device__ float g_ff3[(size_t)NTOK*AHID];
__device__ float g_cos[SEQ*32], g_sin[SEQ*32];

// ---------------------------------------------------------------------------
// PTX helpers
// ---------------------------------------------------------------------------
__device__ __forceinline__ void cp_async16(uint32_t dst, const void* src, int srcbytes) {
    asm volatile("cp.async.cg.shared.global [%0], [%1], 16, %2;\n"
                 :: "r"(dst), "l"(src), "r"(srcbytes));
}
#define CP_COMMIT() asm volatile("cp.async.commit_group;\n" ::)
#define CP_WAIT(n)  asm volatile("cp.async.wait_group %0;\n" :: "n"(n))

#define LDSM4(R0,R1,R2,R3,addr)                                               \
  asm volatile("ldmatrix.sync.aligned.m8n8.x4.shared.b16 {%0,%1,%2,%3}, [%4];"\
               : "=r"(R0),"=r"(R1),"=r"(R2),"=r"(R3) : "r"(addr))

#define MMA16816(d, A0,A1,A2,A3, B0,B1)                                       \
  asm volatile("mma.sync.aligned.m16n8k16.row.col.f32.bf16.bf16.f32 "         \
               "{%0,%1,%2,%3}, {%4,%5,%6,%7}, {%8,%9}, {%0,%1,%2,%3};"        \
               : "+f"(d[0]), "+f"(d[1]), "+f"(d[2]), "+f"(d[3])               \
               : "r"(A0), "r"(A1), "r"(A2), "r"(A3), "r"(B0), "r"(B1))

// ---------------------------------------------------------------------------
// Pipelined bf16 GEMM. A: [M][K] planes (lda). B: [N][K] planes (ldb).
// C = alpha*(A@B^T + bias) (+C if accum). outmode 0: fp32 C; 1: bf16 hi/lo planes.
// ---------------------------------------------------------------------------
__device__ __forceinline__ void load_stage(
    uint32_t sstage,
    const __nv_bfloat16* __restrict__ Abh, const __nv_bfloat16* __restrict__ Abl,
    const __nv_bfloat16* __restrict__ Bbh, const __nv_bfloat16* __restrict__ Bbl,
    int m0, int n0, int k0, int K, int N, int lda, int ldb, int tid)
{
    #pragma unroll
    for (int i = 0; i < 2; i++) {
        int idx = tid + i*256;
        int r = idx >> 2, ch = idx & 3;
        int k = k0 + ch*8;
        int s = (K - k) * 2; s = s < 0 ? 0 : (s > 16 ? 16 : s);
        int kk = s ? k : 0;
        // A planes
        long long aoff = (long long)(m0 + r) * lda + kk;
        uint32_t da = sstage + (uint32_t)(r*SPITCH + ch*8)*2;
        cp_async16(da,                 Abh + aoff, s);
        cp_async16(da + TILE_ELEMS*2,  Abl + aoff, s);
        // B planes
        int n = n0 + r;
        int sb = (n < N) ? s : 0;
        long long boff = (long long)(n < N ? n : 0) * ldb + (sb ? k : 0);
        uint32_t db = sstage + (uint32_t)(2*TILE_ELEMS + r*SPITCH + ch*8)*2;
        cp_async16(db,                 Bbh + boff, sb);
        cp_async16(db + TILE_ELEMS*2,  Bbl + boff, sb);
    }
}

__global__ void __launch_bounds__(256, 1)
gemm_bf16_kernel(const __nv_bfloat16* __restrict__ Ah, const __nv_bfloat16* __restrict__ Al,
                 const __nv_bfloat16* __restrict__ Bh, const __nv_bfloat16* __restrict__ Bl,
                 float* __restrict__ C, __nv_bfloat16* __restrict__ Ch, __nv_bfloat16* __restrict__ Cl,
                 const float* __restrict__ bias,
                 int M, int N, int K, int lda, int ldb, int ldc,
                 float alpha, int accum, int outmode, int bdiv,
                 long long sA1, long long sA2, long long sB1, long long sB2,
                 long long sC1, long long sC2)
{
    extern __shared__ __nv_bfloat16 smem[];
    uint32_t sbase = (uint32_t)__cvta_generic_to_shared(smem);

    const int tid = threadIdx.x, lane = tid & 31, warp = tid >> 5;
    const int wm = warp >> 1, wn = warp & 1;

    const int z = blockIdx.z, zq = z / bdiv, zr = z - zq * bdiv;
    const __nv_bfloat16* Abh = Ah + zq*sA1 + (long long)zr*sA2;
    const __nv_bfloat16* Abl = Al + zq*sA1 + (long long)zr*sA2;
    const __nv_bfloat16* Bbh = Bh + zq*sB1 + (long long)zr*sB2;
    const __nv_bfloat16* Bbl = Bl + zq*sB1 + (long long)zr*sB2;
    const long long coff = zq*sC1 + (long long)zr*sC2;

    const int m0 = blockIdx.y * 128, n0 = blockIdx.x * 128;
    const int T = (K + BK - 1) / BK;

    // prologue: fill NSTAGE-1 stages
    const int npro = (T < NSTAGE-1) ? T : NSTAGE-1;
    for (int s = 0; s < npro; s++) {
        load_stage(sbase + (uint32_t)s*STAGE_ELEMS*2, Abh, Abl, Bbh, Bbl,
                   m0, n0, s*BK, K, N, lda, ldb, tid);
        CP_COMMIT();
    }

    float acc[2][8][4];
    #pragma unroll
    for (int i = 0; i < 2; i++)
        #pragma unroll
        for (int j = 0; j < 8; j++)
            #pragma unroll
            for (int e = 0; e < 4; e++) acc[i][j][e] = 0.f;

    for (int kt = 0; kt < T; kt++) {
        if (kt + NSTAGE - 1 < T) { CP_WAIT(NSTAGE-2); } else { CP_WAIT(0); }
        __syncthreads();
        if (kt + NSTAGE - 1 < T) {
            load_stage(sbase + (uint32_t)(((kt + NSTAGE - 1) % NSTAGE)*STAGE_ELEMS*2),
                       Abh, Abl, Bbh, Bbl, m0, n0, (kt + NSTAGE - 1)*BK, K, N, lda, ldb, tid);
            CP_COMMIT();
        }

        uint32_t st = sbase + (uint32_t)((kt % NSTAGE)*STAGE_ELEMS*2);
        #pragma unroll
        for (int ks = 0; ks < 2; ks++) {
            const int c0 = ks*16 + ((lane >> 4) << 3);
            const int rr = lane & 15;
            uint32_t ah[2][4], al[2][4], bh[8][2], bl[8][2];
            #pragma unroll
            for (int mt = 0; mt < 2; mt++) {
                uint32_t ad = st + (uint32_t)(((wm*32 + mt*16 + rr)*SPITCH + c0)*2);
                LDSM4(ah[mt][0], ah[mt][1], ah[mt][2], ah[mt][3], ad);
                LDSM4(al[mt][0], al[mt][1], al[mt][2], al[mt][3], ad + TILE_ELEMS*2);
            }
            #pragma unroll
            for (int p = 0; p < 4; p++) {
                uint32_t bd = st + (uint32_t)((2*TILE_ELEMS + (wn*64 + p*16 + rr)*SPITCH + c0)*2);
                uint32_t r0, r1, r2, r3;
                LDSM4(r0, r1, r2, r3, bd);
                bh[2*p][0] = r0; bh[2*p+1][0] = r1; bh[2*p][1] = r2; bh[2*p+1][1] = r3;
                LDSM4(r0, r1, r2, r3, bd + TILE_ELEMS*2);
                bl[2*p][0] = r0; bl[2*p+1][0] = r1; bl[2*p][1] = r2; bl[2*p+1][1] = r3;
            }
            #pragma unroll
            for (int mt = 0; mt < 2; mt++)
                #pragma unroll
                for (int nt = 0; nt < 8; nt++) {
                    MMA16816(acc[mt][nt], ah[mt][0],ah[mt][1],ah[mt][2],ah[mt][3], bh[nt][0],bh[nt][1]);
                    MMA16816(acc[mt][nt], ah[mt][0],ah[mt][1],ah[mt][2],ah[mt][3], bl[nt][0],bl[nt][1]);
                    MMA16816(acc[mt][nt], al[mt][0],al[mt][1],al[mt][2],al[mt][3], bh[nt][0],bh[nt][1]);
                }
        }
    }

    // epilogue
    float* Cb = C ? C + coff : nullptr;
    __nv_bfloat16* Chb = Ch ? Ch + coff : nullptr;
    __nv_bfloat16* Clb = Cl ? Cl + coff : nullptr;
    const int g = lane >> 2, t4 = lane & 3;

    #pragma unroll
    for (int mt = 0; mt < 2; mt++)
        #pragma unroll
        for (int nt = 0; nt < 8; nt++) {
            int r = m0 + wm*32 + mt*16 + g;
            int c = n0 + wn*64 + nt*8 + 2*t4;
            if (c < N) {
                float bv0 = 0.f, bv1 = 0.f;
                if (bias) { bv0 = bias[c]; bv1 = bias[c+1]; }
                #pragma unroll
                for (int hh = 0; hh < 2; hh++) {
                    int rr = r + hh*8;
                    float v0 = (acc[mt][nt][hh*2+0] + bv0) * alpha;
                    float v1 = (acc[mt][nt][hh*2+1] + bv1) * alpha;
                    long long off = (long long)rr * ldc + c;
                    if (outmode == 0) {
                        float2 o;
                        if (accum) { float2 p = *(const float2*)(Cb + off); o.x = p.x + v0; o.y = p.y + v1; }
                        else       { o.x = v0; o.y = v1; }
                        *(float2*)(Cb + off) = o;
                    } else {
                        __nv_bfloat16 h0 = __float2bfloat16(v0);
                        __nv_bfloat16 h1 = __float2bfloat16(v1);
                        __nv_bfloat16 l0 = __float2bfloat16(v0 - __bfloat162float(h0));
                        __nv_bfloat16 l1 = __float2bfloat16(v1 - __bfloat162float(h1));
                        uint32_t ph = ((uint32_t)__bfloat16_as_ushort(h1) << 16) | __bfloat16_as_ushort(h0);
                        uint32_t pl = ((uint32_t)__bfloat16_as_ushort(l1) << 16) | __bfloat16_as_ushort(l0);
                        *(uint32_t*)(Chb + off) = ph;
                        *(uint32_t*)(Clb + off) = pl;
                    }
                }
            }
        }
}

// ---------------------------------------------------------------------------
// Producers / converters
// ---------------------------------------------------------------------------
__global__ void split_kernel(const float* __restrict__ src,
                             __nv_bfloat16* __restrict__ dh,
                             __nv_bfloat16* __restrict__ dl, long long n)
{
    long long i = (long long)blockIdx.x * blockDim.x + threadIdx.x;
    if (i >= n) return;
    float v = src[i];
    __nv_bfloat16 hi = __float2bfloat16(v);
    dh[i] = hi;
    dl[i] = __float2bfloat16(v - __bfloat162float(hi));
}

// transpose fp32 [R][C] -> bf16 planes [C][pitch>=R]
__global__ void transpose_split_kernel(const float* __restrict__ src,
                                       __nv_bfloat16* __restrict__ dh,
                                       __nv_bfloat16* __restrict__ dl,
                                       int R, int C, int dstPitch,
                                       long long srcZ, long long dstZ)
{
    __shared__ float t[32][33];
    long long so = (long long)blockIdx.z * srcZ;
    long long dofs = (long long)blockIdx.z * dstZ;
    int c0 = blockIdx.x*32, r0 = blockIdx.y*32;
    #pragma unroll
    for (int i = threadIdx.y; i < 32; i += 8) {
        int r = r0 + i, c = c0 + threadIdx.x;
        t[i][threadIdx.x] = (r < R && c < C) ? src[so + (long long)r*C + c] : 0.f;
    }
    __syncthreads();
    #pragma unroll
    for (int i = threadIdx.y; i < 32; i += 8) {
        int c = c0 + i, r = r0 + threadIdx.x;
        if (c < C && r < R) {
            float v = t[threadIdx.x][i];
            __nv_bfloat16 hi = __float2bfloat16(v);
            long long o = dofs + (long long)c*dstPitch + r;
            dh[o] = hi;
            dl[o] = __float2bfloat16(v - __bfloat162float(hi));
        }
    }
}

__global__ void rmsnorm_kernel(const float* __restrict__ x, const float* __restrict__ w,
                               __nv_bfloat16* __restrict__ oh, __nv_bfloat16* __restrict__ ol)
{
    long long row = blockIdx.x;
    const float* xr = x + row * HID;
    float s = 0.f;
    #pragma unroll
    for (int c = threadIdx.x; c < HID; c += 256) { float v = xr[c]; s += v * v; }
    #pragma unroll
    for (int o = 16; o; o >>= 1) s += __shfl_xor_sync(0xffffffffu, s, o);
    __shared__ float red[8];
    int warp = threadIdx.x >> 5, lane = threadIdx.x & 31;
    if (lane == 0) red[warp] = s;
    __syncthreads();
    float tot = red[0]+red[1]+red[2]+red[3]+red[4]+red[5]+red[6]+red[7];
    float inv = rsqrtf(tot * (1.0f / HID) + RMSEPS);
    #pragma unroll
    for (int c = threadIdx.x; c < HID; c += 256) {
        float v = xr[c] * inv * w[c];
        __nv_bfloat16 hi = __float2bfloat16(v);
        oh[row*HID + c] = hi;
        ol[row*HID + c] = __float2bfloat16(v - __bfloat162float(hi));
    }
}

__global__ void rope_cache_kernel()
{
    int i = blockIdx.x * blockDim.x + threadIdx.x;
    if (i >= SEQ * 32) return;
    int s = i >> 5, j = i & 31;
    float invf = expf(-(float)j * (1.0f / 32.0f) * logf(10000.0f));
    float a = (float)s * invf;
    g_cos[i] = cosf(a);
    g_sin[i] = sinf(a);
}

__global__ void rope_apply_kernel(const float* __restrict__ qf, const float* __restrict__ kf)
{
    int i = blockIdx.x * blockDim.x + threadIdx.x;      // NTOK*NHEAD*32
    if (i >= NTOK * NHEAD * 32) return;
    int m = i >> 9, rem = i & 511;
    int h = rem >> 5, j = rem & 31;
    int s = m & (SEQ - 1);
    float c  = g_cos[s*32 + j];
    float sn = g_sin[s*32 + j];
    long long base = (long long)m * HID + h * HEADDIM + j;
    {
        float a = qf[base], b = qf[base + 32];
        float v0 = a * c - b * sn, v1 = b * c + a * sn;
        __nv_bfloat16 h0 = __float2bfloat16(v0), h1 = __float2bfloat16(v1);
        g_qh[base]      = h0; g_ql[base]      = __float2bfloat16(v0 - __bfloat162float(h0));
        g_qh[base + 32] = h1; g_ql[base + 32] = __float2bfloat16(v1 - __bfloat162float(h1));
    }
    {
        float a = kf[base], b = kf[base + 32];
        float v0 = a * c - b * sn, v1 = b * c + a * sn;
        __nv_bfloat16 h0 = __float2bfloat16(v0), h1 = __float2bfloat16(v1);
        g_kh[base]      = h0; g_kl[base]      = __float2bfloat16(v0 - __bfloat162float(h0));
        g_kh[base + 32] = h1; g_kl[base + 32] = __float2bfloat16(v1 - __bfloat162float(h1));
    }
}

__global__ void softmax_kernel(const float* __restrict__ sc,
                               __nv_bfloat16* __restrict__ ph, __nv_bfloat16* __restrict__ pl)
{
    long long row = (long long)blockIdx.x * 8 + (threadIdx.x >> 5);
    int lane = threadIdx.x & 31;
    const float* p = sc + row * SEQ;
    float e[16];
    float mx = -3.4e38f;
    #pragma unroll
    for (int i = 0; i < 16; i++) { e[i] = p[lane + i*32]; mx = fmaxf(mx, e[i]); }
    #pragma unroll
    for (int o = 16; o; o >>= 1) mx = fmaxf(mx, __shfl_xor_sync(0xffffffffu, mx, o));
    float sum = 0.f;
    #pragma unroll
    for (int i = 0; i < 16; i++) { e[i] = __expf(e[i] - mx); sum += e[i]; }
    #pragma unroll
    for (int o = 16; o; o >>= 1) sum += __shfl_xor_sync(0xffffffffu, sum, o);
    float r = 1.0f / sum;
    #pragma unroll
    for (int i = 0; i < 16; i++) {
        float v = e[i] * r;
        __nv_bfloat16 hi = __float2bfloat16(v);
        ph[row*SEQ + lane + i*32] = hi;
        pl[row*SEQ + lane + i*32] = __float2bfloat16(v - __bfloat162float(hi));
    }
}

__global__ void swiglu_kernel(const float* __restrict__ f1, const float* __restrict__ f3,
                              __nv_bfloat16* __restrict__ oh, __nv_bfloat16* __restrict__ ol)
{
    long long i = (long long)blockIdx.x * blockDim.x + threadIdx.x;
    if (i >= (long long)NTOK * AHID) return;
    long long r = i / AHID;
    int c = (int)(i - r * AHID);
    float a = f1[i], b = f3[i];
    float v = a / (1.0f + __expf(-a)) * b;
    __nv_bfloat16 hi = __float2bfloat16(v);
    long long o = r * APAD + c;
    oh[o] = hi;
    ol[o] = __float2bfloat16(v - __bfloat162float(hi));
}

// ---------------------------------------------------------------------------
// Host plumbing
// ---------------------------------------------------------------------------
static void gemm(const __nv_bfloat16* Ahp, const __nv_bfloat16* Alp,
                 const __nv_bfloat16* Bhp, const __nv_bfloat16* Blp,
                 float* C, __nv_bfloat16* Ch, __nv_bfloat16* Cl,
                 const float* bias, int M, int N, int K, int lda, int ldb, int ldc,
                 float alpha, int accum, int outmode,
                 int batches = 1, int bdiv = 1,
                 long long sA1 = 0, long long sA2 = 0,
                 long long sB1 = 0, long long sB2 = 0,
                 long long sC1 = 0, long long sC2 = 0)
{
    dim3 grid((N + 127) / 128, M / 128, batches);
    gemm_bf16_kernel<<<grid, 256, SMEM_BYTES>>>(Ahp, Alp, Bhp, Blp, C, Ch, Cl, bias,
                                                M, N, K, lda, ldb, ldc, alpha, accum, outmode,
                                                bdiv, sA1, sA2, sB1, sB2, sC1, sC2);
}

#define SYM(p, s) cudaGetSymbolAddress((void**)&p, s)

extern "C" void kernel_launch(void* const* d_in, const int* in_sizes, int n_in,
                              void* d_out, int out_size)
{
    const float* x       = (const float*)d_in[0];
    const float* in_w    = (const float*)d_in[1];
    const float* in_b    = (const float*)d_in[2];
    const float* norm1_w = (const float*)d_in[3];
    const float* norm2_w = (const float*)d_in[4];
    const float* wq      = (const float*)d_in[5];
    const float* bq      = (const float*)d_in[6];
    const float* wk      = (const float*)d_in[7];
    const float* bk      = (const float*)d_in[8];
    const float* wv      = (const float*)d_in[9];
    const float* bv      = (const float*)d_in[10];
    const float* wo      = (const float*)d_in[11];
    const float* bo      = (const float*)d_in[12];
    const float* w1      = (const float*)d_in[13];
    const float* b1      = (const float*)d_in[14];
    const float* w3      = (const float*)d_in[15];
    const float* b3      = (const float*)d_in[16];
    const float* w2      = (const float*)d_in[17];
    const float* b2      = (const float*)d_in[18];
    const float* onorm_w = (const float*)d_in[19];
    const float* out_w   = (const float*)d_in[20];
    const float* out_b   = (const float*)d_in[21];
    float* out = (float*)d_out;

    cudaFuncSetAttribute(gemm_bf16_kernel,
                         cudaFuncAttributeMaxDynamicSharedMemorySize, SMEM_BYTES);

    __nv_bfloat16 *winh,*winl,*wqh,*wql,*wkh,*wkl,*wvh,*wvl,*woh,*wol;
    __nv_bfloat16 *w1h,*w1l,*w3h,*w3l,*w2h,*w2l,*outwh,*outwl;
    __nv_bfloat16 *xh,*xl,*gh,*gl,*qh,*ql,*kh,*kl,*vth,*vtl,*oh,*ol,*ph,*pl,*ffh,*ffl;
    float *h,*qf,*kf,*vf,*sc,*ff1,*ff3;
    SYM(winh,g_winh); SYM(winl,g_winl);
    SYM(wqh,g_wqh); SYM(wql,g_wql); SYM(wkh,g_wkh); SYM(wkl,g_wkl);
    SYM(wvh,g_wvh); SYM(wvl,g_wvl); SYM(woh,g_woh); SYM(wol,g_wol);
    SYM(w1h,g_w1h); SYM(w1l,g_w1l); SYM(w3h,g_w3h); SYM(w3l,g_w3l);
    SYM(w2h,g_w2h); SYM(w2l,g_w2l); SYM(outwh,g_outwh); SYM(outwl,g_outwl);
    SYM(xh,g_xh); SYM(xl,g_xl); SYM(gh,g_gh); SYM(gl,g_gl);
    SYM(qh,g_qh); SYM(ql,g_ql); SYM(kh,g_kh); SYM(kl,g_kl);
    SYM(vth,g_vth); SYM(vtl,g_vtl); SYM(oh,g_oh); SYM(ol,g_ol);
    SYM(ph,g_ph); SYM(pl,g_pl); SYM(ffh,g_ffh); SYM(ffl,g_ffl);
    SYM(h,g_h); SYM(qf,g_qf); SYM(kf,g_kf); SYM(vf,g_vf);
    SYM(sc,g_sc); SYM(ff1,g_ff1); SYM(ff3,g_ff3);

    const long long HH = (long long)HID*HID;
    const long long HA = (long long)HID*AHID;

    // ---- one-time converters ----
    rope_cache_kernel<<<(SEQ*32 + 255)/256, 256>>>();
    split_kernel<<<(1048576 + 255)/256, 256>>>(x, xh, xl, 1048576);
    {   // weights: transpose-convert to [N][K]
        dim3 b(32, 8);
        transpose_split_kernel<<<dim3(32, 4, 1),  b>>>(in_w,  winh, winl, DIM,  HID, DIM,  0, 0);
        transpose_split_kernel<<<dim3(32, 32, 6), b>>>(wq,    wqh,  wql,  HID,  HID, HID,  HH, HH);
        transpose_split_kernel<<<dim3(32, 32, 6), b>>>(wk,    wkh,  wkl,  HID,  HID, HID,  HH, HH);
        transpose_split_kernel<<<dim3(32, 32, 6), b>>>(wv,    wvh,  wvl,  HID,  HID, HID,  HH, HH);
        transpose_split_kernel<<<dim3(32, 32, 6), b>>>(wo,    woh,  wol,  HID,  HID, HID,  HH, HH);
        transpose_split_kernel<<<dim3(86, 32, 6), b>>>(w1,    w1h,  w1l,  HID,  AHID, HID, HA, HA);
        transpose_split_kernel<<<dim3(86, 32, 6), b>>>(w3,    w3h,  w3l,  HID,  AHID, HID, HA, HA);
        transpose_split_kernel<<<dim3(32, 86, 6), b>>>(w2,    w2h,  w2l,  AHID, HID, APAD, HA, (long long)HID*APAD);
        transpose_split_kernel<<<dim3(4, 32, 1),  b>>>(out_w, outwh, outwl, HID, DIM, HID, 0, 0);
    }

    // h = x @ in_w + in_b
    gemm(xh, xl, winh, winl, h, nullptr, nullptr, in_b,
         NTOK, HID, DIM, DIM, DIM, HID, 1.0f, 0, 0);

    for (int l = 0; l < NLAYER; l++) {
        rmsnorm_kernel<<<NTOK, 256>>>(h, norm1_w + (long long)l*HID, gh, gl);

        gemm(gh, gl, wqh + l*HH, wql + l*HH, qf, nullptr, nullptr, bq + (long long)l*HID,
             NTOK, HID, HID, HID, HID, HID, 1.0f, 0, 0);
        gemm(gh, gl, wkh + l*HH, wkl + l*HH, kf, nullptr, nullptr, bk + (long long)l*HID,
             NTOK, HID, HID, HID, HID, HID, 1.0f, 0, 0);
        gemm(gh, gl, wvh + l*HH, wvl + l*HH, vf, nullptr, nullptr, bv + (long long)l*HID,
             NTOK, HID, HID, HID, HID, HID, 1.0f, 0, 0);

        rope_apply_kernel<<<(NTOK*NHEAD*32 + 255)/256, 256>>>(qf, kf);
        transpose_split_kernel<<<dim3(32, 256, 1), dim3(32,8)>>>(vf, vth, vtl, NTOK, HID, NTOK, 0, 0);

        // scores = 0.125 * Q K^T      z = b*16 + head
        gemm(qh, ql, kh, kl, sc, nullptr, nullptr, nullptr,
             SEQ, SEQ, HEADDIM, HID, HID, SEQ, 0.125f, 0, 0,
             BATCH*NHEAD, NHEAD,
             (long long)SEQ*HID, HEADDIM,
             (long long)SEQ*HID, HEADDIM,
             (long long)NHEAD*SEQ*SEQ, (long long)SEQ*SEQ);

        softmax_kernel<<<BATCH*NHEAD*SEQ/8, 256>>>(sc, ph, pl);

        // o = P @ V  -> o planes ([token][HID] slices)
        gemm(ph, pl, vth, vtl, nullptr, oh, ol, nullptr,
             SEQ, HEADDIM, SEQ, SEQ, NTOK, HID, 1.0f, 0, 1,
             BATCH*NHEAD, NHEAD,
             (long long)NHEAD*SEQ*SEQ, (long long)SEQ*SEQ,
             (long long)SEQ, (long long)HEADDIM*NTOK,
             (long long)SEQ*HID, (long long)HEADDIM);

        // h += (o @ wo + bo) * RS
        gemm(oh, ol, woh + l*HH, wol + l*HH, h, nullptr, nullptr, bo + (long long)l*HID,
             NTOK, HID, HID, HID, HID, HID, RSCALE, 1, 0);

        rmsnorm_kernel<<<NTOK, 256>>>(h, norm2_w + (long long)l*HID, gh, gl);

        gemm(gh, gl, w1h + l*HA, w1l + l*HA, ff1, nullptr, nullptr, b1 + (long long)l*AHID,
             NTOK, AHID, HID, HID, HID, AHID, 1.0f, 0, 0);
        gemm(gh, gl, w3h + l*HA, w3l + l*HA, ff3, nullptr, nullptr, b3 + (long long)l*AHID,
             NTOK, AHID, HID, HID, HID, AHID, 1.0f, 0, 0);

        {
            long long n = (long long)NTOK * AHID;
            swiglu_kernel<<<(unsigned)((n + 255) / 256), 256>>>(ff1, ff3, ffh, ffl);
        }

        // h += (ffg @ w2 + b2) * RS
        gemm(ffh, ffl, w2h + (long long)l*HID*APAD, w2l + (long long)l*HID*APAD, h,
             nullptr, nullptr, b2 + (long long)l*HID,
             NTOK, HID, AHID, APAD, APAD, HID, RSCALE, 1, 0);
    }

    rmsnorm_kernel<<<NTOK, 256>>>(h, onorm_w, gh, gl);
    gemm(gh, gl, outwh, outwl, out, nullptr, nullptr, out_b,
         NTOK, DIM, HID, HID, HID, DIM, 1.0f, 0, 0);
}

// round 4
// speedup vs baseline: 1.8029x; 1.1357x over previous
#include <cuda_runtime.h>
#include <cuda_bf16.h>
#include <cstdint>

#define BATCH   16
#define SEQ     512
#define DIM     128
#define HID     1024
#define NLAYER  6
#define NHEAD   16
#define HEADDIM 64
#define AHID    2730
#define APAD    2736
#define FPAD    5472              // row pitch for fused ff13 fp32 buffer
#define NTOK    8192
#define RSCALE  0.4082482904638630f
#define RMSEPS  1e-6f

#define SPITCH  40                // bf16 elems per smem row (80B, conflict-free)
#define NSTAGE  3

// ---------------------------------------------------------------------------
// Device scratch (allocation-free)
// ---------------------------------------------------------------------------
__device__ __nv_bfloat16 g_winh[131072],       g_winl[131072];
__device__ __nv_bfloat16 g_wqkvh[6*3145728],   g_wqkvl[6*3145728];   // [3072][1024]
__device__ __nv_bfloat16 g_woh [6*1048576],    g_wol [6*1048576];
__device__ __nv_bfloat16 g_w13h[6*5591040],    g_w13l[6*5591040];    // [5460][1024]
__device__ __nv_bfloat16 g_w2h [6*1024*APAD],  g_w2l [6*1024*APAD];  // [1024][APAD]
__device__ __nv_bfloat16 g_outwh[131072],      g_outwl[131072];
__device__ __nv_bfloat16 g_xh [1048576],       g_xl [1048576];
__device__ __nv_bfloat16 g_gh [8388608],       g_gl [8388608];
__device__ __nv_bfloat16 g_qh [8388608],       g_ql [8388608];
__device__ __nv_bfloat16 g_kh [8388608],       g_kl [8388608];
__device__ __nv_bfloat16 g_vth[8388608],       g_vtl[8388608];       // [HID][NTOK]
__device__ __nv_bfloat16 g_oh [8388608],       g_ol [8388608];
__device__ __nv_bfloat16 g_ph [67108864],      g_pl [67108864];
__device__ __nv_bfloat16 g_ffh[(size_t)NTOK*APAD], g_ffl[(size_t)NTOK*APAD];
__device__ float g_h   [8388608];
__device__ float g_qkvf[(size_t)NTOK*3072];
__device__ float g_sc  [67108864];
__device__ float g_ff13[(size_t)NTOK*FPAD];
__device__ float g_bqkv[6*3072];
__device__ float g_b13 [6*5460];
__device__ float g_cos [SEQ*32], g_sin[SEQ*32];

// ---------------------------------------------------------------------------
// PTX helpers
// ---------------------------------------------------------------------------
__device__ __forceinline__ void cp_async16(uint32_t dst, const void* src, int srcbytes) {
    asm volatile("cp.async.cg.shared.global [%0], [%1], 16, %2;\n"
                 :: "r"(dst), "l"(src), "r"(srcbytes));
}
#define CP_COMMIT() asm volatile("cp.async.commit_group;\n" ::)
#define CP_WAIT(n)  asm volatile("cp.async.wait_group %0;\n" :: "n"(n))

#define LDSM4(R0,R1,R2,R3,addr)                                               \
  asm volatile("ldmatrix.sync.aligned.m8n8.x4.shared.b16 {%0,%1,%2,%3}, [%4];"\
               : "=r"(R0),"=r"(R1),"=r"(R2),"=r"(R3) : "r"(addr))

#define MMA16816(d, A0,A1,A2,A3, B0,B1)                                       \
  asm volatile("mma.sync.aligned.m16n8k16.row.col.f32.bf16.bf16.f32 "         \
               "{%0,%1,%2,%3}, {%4,%5,%6,%7}, {%8,%9}, {%0,%1,%2,%3};"        \
               : "+f"(d[0]), "+f"(d[1]), "+f"(d[2]), "+f"(d[3])               \
               : "r"(A0), "r"(A1), "r"(A2), "r"(A3), "r"(B0), "r"(B1))

// ---------------------------------------------------------------------------
// Pipelined bf16 split GEMM (template over CTA tile width / warp grid).
// A: [M][K] hi/lo planes (lda). B: [N][K] hi/lo planes (ldb).
// C = alpha*(A@B^T + bias) (+C if accum). outmode 0: fp32; 1: bf16 hi/lo planes.
// ---------------------------------------------------------------------------
template<int NT, int WR, int WC>
__global__ void __launch_bounds__(256, 1)
gemm_mma_kernel(const __nv_bfloat16* __restrict__ Ah, const __nv_bfloat16* __restrict__ Al,
                const __nv_bfloat16* __restrict__ Bh, const __nv_bfloat16* __restrict__ Bl,
                float* __restrict__ C, __nv_bfloat16* __restrict__ Ch, __nv_bfloat16* __restrict__ Cl,
                const float* __restrict__ bias,
                int M, int N, int K, int lda, int ldb, int ldc,
                float alpha, int accum, int outmode, int bdiv,
                long long sA1, long long sA2, long long sB1, long long sB2,
                long long sC1, long long sC2)
{
    constexpr int WTM = 128 / WR;          // warp tile M
    constexpr int WTN = NT / WC;           // warp tile N
    constexpr int MT  = WTM / 16;
    constexpr int NTT = WTN / 8;
    constexpr int NH  = NTT / 4;           // B-fragment half-groups
    constexpr int APLANE = 128 * SPITCH;   // elems
    constexpr int BPLANE = NT * SPITCH;
    constexpr int STAGE_E = 2*APLANE + 2*BPLANE;

    extern __shared__ __nv_bfloat16 smem[];
    uint32_t sbase = (uint32_t)__cvta_generic_to_shared(smem);

    const int tid = threadIdx.x, lane = tid & 31, warp = tid >> 5;
    const int wm = warp / WC, wn = warp % WC;

    const int z = blockIdx.z, zq = z / bdiv, zr = z - zq * bdiv;
    const __nv_bfloat16* Abh = Ah + zq*sA1 + (long long)zr*sA2;
    const __nv_bfloat16* Abl = Al + zq*sA1 + (long long)zr*sA2;
    const __nv_bfloat16* Bbh = Bh + zq*sB1 + (long long)zr*sB2;
    const __nv_bfloat16* Bbl = Bl + zq*sB1 + (long long)zr*sB2;
    const long long coff = zq*sC1 + (long long)zr*sC2;

    const int m0 = blockIdx.y * 128, n0 = blockIdx.x * NT;
    const int T = (K + 31) >> 5;

    auto load_stage = [&](int stg, int k0) {
        uint32_t st = sbase + (uint32_t)stg * (STAGE_E * 2);
        #pragma unroll
        for (int i = 0; i < 2; i++) {               // A: 128 rows x 4 chunks
            int idx = tid + i*256;
            int r = idx >> 2, ch = idx & 3;
            int k = k0 + ch*8;
            int s = (K - k) * 2; s = s < 0 ? 0 : (s > 16 ? 16 : s);
            long long aoff = (long long)(m0 + r) * lda + (s ? k : 0);
            uint32_t d = st + (uint32_t)(r*SPITCH + ch*8)*2;
            cp_async16(d,            Abh + aoff, s);
            cp_async16(d + APLANE*2, Abl + aoff, s);
        }
        #pragma unroll
        for (int i = 0; i < NT/64; i++) {           // B: NT rows x 4 chunks
            int idx = tid + i*256;
            int r = idx >> 2, ch = idx & 3;
            int n = n0 + r;
            int k = k0 + ch*8;
            int s = (K - k) * 2; s = s < 0 ? 0 : (s > 16 ? 16 : s);
            if (n >= N) s = 0;
            long long boff = (long long)(n < N ? n : 0) * ldb + (s ? k : 0);
            uint32_t d = st + (uint32_t)(2*APLANE + r*SPITCH + ch*8)*2;
            cp_async16(d,            Bbh + boff, s);
            cp_async16(d + BPLANE*2, Bbl + boff, s);
        }
    };

    // prologue
    load_stage(0, 0);
    CP_COMMIT();
    if (T > 1) { load_stage(1, 32); CP_COMMIT(); }

    float acc[MT][NTT][4];
    #pragma unroll
    for (int i = 0; i < MT; i++)
        #pragma unroll
        for (int j = 0; j < NTT; j++)
            #pragma unroll
            for (int e = 0; e < 4; e++) acc[i][j][e] = 0.f;

    for (int kt = 0; kt < T; kt++) {
        if (kt + 1 < T) { CP_WAIT(1); } else { CP_WAIT(0); }
        __syncthreads();
        if (kt + 2 < T) { load_stage((kt + 2) % NSTAGE, (kt + 2) * 32); CP_COMMIT(); }

        uint32_t st = sbase + (uint32_t)((kt % NSTAGE) * (STAGE_E * 2));
        #pragma unroll
        for (int ks = 0; ks < 2; ks++) {
            const int c0 = ks*16 + ((lane >> 4) << 3);
            const int rr = lane & 15;
            uint32_t ah[MT][4], al[MT][4];
            #pragma unroll
            for (int mt = 0; mt < MT; mt++) {
                uint32_t ad = st + (uint32_t)(((wm*WTM + mt*16 + rr)*SPITCH + c0)*2);
                LDSM4(ah[mt][0], ah[mt][1], ah[mt][2], ah[mt][3], ad);
                LDSM4(al[mt][0], al[mt][1], al[mt][2], al[mt][3], ad + APLANE*2);
            }
            #pragma unroll
            for (int half = 0; half < NH; half++) {
                uint32_t bh[4][2], bl[4][2];
                #pragma unroll
                for (int p = 0; p < 2; p++) {
                    uint32_t bd = st + (uint32_t)((2*APLANE +
                                  (wn*WTN + half*32 + p*16 + rr)*SPITCH + c0)*2);
                    uint32_t r0, r1, r2, r3;
                    LDSM4(r0, r1, r2, r3, bd);
                    bh[2*p][0] = r0; bh[2*p+1][0] = r1; bh[2*p][1] = r2; bh[2*p+1][1] = r3;
                    LDSM4(r0, r1, r2, r3, bd + BPLANE*2);
                    bl[2*p][0] = r0; bl[2*p+1][0] = r1; bl[2*p][1] = r2; bl[2*p+1][1] = r3;
                }
                #pragma unroll
                for (int mt = 0; mt < MT; mt++)
                    #pragma unroll
                    for (int j = 0; j < 4; j++) {
                        int nt = half*4 + j;
                        MMA16816(acc[mt][nt], ah[mt][0],ah[mt][1],ah[mt][2],ah[mt][3], bh[j][0],bh[j][1]);
                        MMA16816(acc[mt][nt], ah[mt][0],ah[mt][1],ah[mt][2],ah[mt][3], bl[j][0],bl[j][1]);
                        MMA16816(acc[mt][nt], al[mt][0],al[mt][1],al[mt][2],al[mt][3], bh[j][0],bh[j][1]);
                    }
            }
        }
    }

    // ---- epilogue ----
    const int g = lane >> 2, t4 = lane & 3;
    #pragma unroll
    for (int mt = 0; mt < MT; mt++)
        #pragma unroll
        for (int nt = 0; nt < NTT; nt++) {
            int r = m0 + wm*WTM + mt*16 + g;
            int c = n0 + wn*WTN + nt*8 + 2*t4;
            if (c < N) {
                float bv0 = 0.f, bv1 = 0.f;
                if (bias) { bv0 = bias[c]; bv1 = bias[c+1]; }
                #pragma unroll
                for (int hh = 0; hh < 2; hh++) {
                    int rr = r + hh*8;
                    float v0 = (acc[mt][nt][hh*2+0] + bv0) * alpha;
                    float v1 = (acc[mt][nt][hh*2+1] + bv1) * alpha;
                    long long off = coff + (long long)rr * ldc + c;
                    if (outmode == 0) {
                        float2 o;
                        if (accum) { float2 p = *(const float2*)(C + off); o.x = p.x + v0; o.y = p.y + v1; }
                        else       { o.x = v0; o.y = v1; }
                        *(float2*)(C + off) = o;
                    } else {
                        __nv_bfloat16 h0 = __float2bfloat16(v0);
                        __nv_bfloat16 h1 = __float2bfloat16(v1);
                        __nv_bfloat16 l0 = __float2bfloat16(v0 - __bfloat162float(h0));
                        __nv_bfloat16 l1 = __float2bfloat16(v1 - __bfloat162float(h1));
                        uint32_t ph = ((uint32_t)__bfloat16_as_ushort(h1) << 16) | __bfloat16_as_ushort(h0);
                        uint32_t pl = ((uint32_t)__bfloat16_as_ushort(l1) << 16) | __bfloat16_as_ushort(l0);
                        *(uint32_t*)(Ch + off) = ph;
                        *(uint32_t*)(Cl + off) = pl;
                    }
                }
            }
        }
}

// ---------------------------------------------------------------------------
// Producers / converters
// ---------------------------------------------------------------------------
__global__ void split_kernel(const float* __restrict__ src,
                             __nv_bfloat16* __restrict__ dh,
                             __nv_bfloat16* __restrict__ dl, long long n)
{
    long long i = (long long)blockIdx.x * blockDim.x + threadIdx.x;
    if (i >= n) return;
    float v = src[i];
    __nv_bfloat16 hi = __float2bfloat16(v);
    dh[i] = hi;
    dl[i] = __float2bfloat16(v - __bfloat162float(hi));
}

// transpose fp32 [R][srcPitch] (first C cols valid) -> bf16 planes [C][dstPitch]
__global__ void transpose_split_kernel(const float* __restrict__ src,
                                       __nv_bfloat16* __restrict__ dh,
                                       __nv_bfloat16* __restrict__ dl,
                                       int R, int C, int srcPitch, int dstPitch,
                                       long long srcZ, long long dstZ)
{
    __shared__ float t[32][33];
    long long so = (long long)blockIdx.z * srcZ;
    long long dofs = (long long)blockIdx.z * dstZ;
    int c0 = blockIdx.x*32, r0 = blockIdx.y*32;
    #pragma unroll
    for (int i = threadIdx.y; i < 32; i += 8) {
        int r = r0 + i, c = c0 + threadIdx.x;
        t[i][threadIdx.x] = (r < R && c < C) ? src[so + (long long)r*srcPitch + c] : 0.f;
    }
    __syncthreads();
    #pragma unroll
    for (int i = threadIdx.y; i < 32; i += 8) {
        int c = c0 + i, r = r0 + threadIdx.x;
        if (c < C && r < R) {
            float v = t[threadIdx.x][i];
            __nv_bfloat16 hi = __float2bfloat16(v);
            long long o = dofs + (long long)c*dstPitch + r;
            dh[o] = hi;
            dl[o] = __float2bfloat16(v - __bfloat162float(hi));
        }
    }
}

__global__ void rmsnorm_kernel(const float* __restrict__ x, const float* __restrict__ w,
                               __nv_bfloat16* __restrict__ oh, __nv_bfloat16* __restrict__ ol)
{
    long long row = blockIdx.x;
    const float* xr = x + row * HID;
    float s = 0.f;
    #pragma unroll
    for (int c = threadIdx.x; c < HID; c += 256) { float v = xr[c]; s += v * v; }
    #pragma unroll
    for (int o = 16; o; o >>= 1) s += __shfl_xor_sync(0xffffffffu, s, o);
    __shared__ float red[8];
    int warp = threadIdx.x >> 5, lane = threadIdx.x & 31;
    if (lane == 0) red[warp] = s;
    __syncthreads();
    float tot = red[0]+red[1]+red[2]+red[3]+red[4]+red[5]+red[6]+red[7];
    float inv = rsqrtf(tot * (1.0f / HID) + RMSEPS);
    #pragma unroll
    for (int c = threadIdx.x; c < HID; c += 256) {
        float v = xr[c] * inv * w[c];
        __nv_bfloat16 hi = __float2bfloat16(v);
        oh[row*HID + c] = hi;
        ol[row*HID + c] = __float2bfloat16(v - __bfloat162float(hi));
    }
}

__global__ void rope_cache_kernel()
{
    int i = blockIdx.x * blockDim.x + threadIdx.x;
    if (i >= SEQ * 32) return;
    int s = i >> 5, j = i & 31;
    float invf = expf(-(float)j * (1.0f / 32.0f) * logf(10000.0f));
    float a = (float)s * invf;
    g_cos[i] = cosf(a);
    g_sin[i] = sinf(a);
}

// reads fused qkv buffer [NTOK][3072]; writes roped q,k into hi/lo planes [NTOK][HID]
__global__ void rope_apply_kernel(const float* __restrict__ qkv)
{
    int i = blockIdx.x * blockDim.x + threadIdx.x;
    if (i >= NTOK * NHEAD * 32) return;
    int m = i >> 9, rem = i & 511;
    int h = rem >> 5, j = rem & 31;
    int s = m & (SEQ - 1);
    float c  = g_cos[s*32 + j];
    float sn = g_sin[s*32 + j];
    long long src = (long long)m * 3072 + h * HEADDIM + j;
    long long dst = (long long)m * HID  + h * HEADDIM + j;
    {
        float a = qkv[src], b = qkv[src + 32];
        float v0 = a * c - b * sn, v1 = b * c + a * sn;
        __nv_bfloat16 h0 = __float2bfloat16(v0), h1 = __float2bfloat16(v1);
        g_qh[dst]      = h0; g_ql[dst]      = __float2bfloat16(v0 - __bfloat162float(h0));
        g_qh[dst + 32] = h1; g_ql[dst + 32] = __float2bfloat16(v1 - __bfloat162float(h1));
    }
    {
        float a = qkv[src + HID], b = qkv[src + HID + 32];
        float v0 = a * c - b * sn, v1 = b * c + a * sn;
        __nv_bfloat16 h0 = __float2bfloat16(v0), h1 = __float2bfloat16(v1);
        g_kh[dst]      = h0; g_kl[dst]      = __float2bfloat16(v0 - __bfloat162float(h0));
        g_kh[dst + 32] = h1; g_kl[dst + 32] = __float2bfloat16(v1 - __bfloat162float(h1));
    }
}

__global__ void softmax_kernel(const float* __restrict__ sc,
                               __nv_bfloat16* __restrict__ ph, __nv_bfloat16* __restrict__ pl)
{
    long long row = (long long)blockIdx.x * 8 + (threadIdx.x >> 5);
    int lane = threadIdx.x & 31;
    const float* p = sc + row * SEQ;
    float e[16];
    float mx = -3.4e38f;
    #pragma unroll
    for (int i = 0; i < 16; i++) { e[i] = p[lane + i*32]; mx = fmaxf(mx, e[i]); }
    #pragma unroll
    for (int o = 16; o; o >>= 1) mx = fmaxf(mx, __shfl_xor_sync(0xffffffffu, mx, o));
    float sum = 0.f;
    #pragma unroll
    for (int i = 0; i < 16; i++) { e[i] = __expf(e[i] - mx); sum += e[i]; }
    #pragma unroll
    for (int o = 16; o; o >>= 1) sum += __shfl_xor_sync(0xffffffffu, sum, o);
    float r = 1.0f / sum;
    #pragma unroll
    for (int i = 0; i < 16; i++) {
        float v = e[i] * r;
        __nv_bfloat16 hi = __float2bfloat16(v);
        ph[row*SEQ + lane + i*32] = hi;
        pl[row*SEQ + lane + i*32] = __float2bfloat16(v - __bfloat162float(hi));
    }
}

// reads fused ff13 [NTOK][FPAD] (w1 out at cols [0,AHID), w3 out at [AHID,2*AHID))
__global__ void swiglu_kernel(const float* __restrict__ ff,
                              __nv_bfloat16* __restrict__ oh, __nv_bfloat16* __restrict__ ol)
{
    long long i = (long long)blockIdx.x * blockDim.x + threadIdx.x;
    if (i >= (long long)NTOK * AHID) return;
    long long r = i / AHID;
    int c = (int)(i - r * AHID);
    float a = ff[r*FPAD + c], b = ff[r*FPAD + AHID + c];
    float v = a / (1.0f + __expf(-a)) * b;
    __nv_bfloat16 hi = __float2bfloat16(v);
    long long o = r * APAD + c;
    oh[o] = hi;
    ol[o] = __float2bfloat16(v - __bfloat162float(hi));
}

// concat per-layer biases: dst[l][0:n1)=b1[l], [n1:n1+n2)=b2[l], [..+n3)=b3[l]
__global__ void concat_bias_kernel(const float* __restrict__ b1, const float* __restrict__ b2,
                                   const float* __restrict__ b3, float* __restrict__ dst,
                                   int n1, int n2, int n3)
{
    int tot = n1 + n2 + n3;
    int i = blockIdx.x * blockDim.x + threadIdx.x;
    if (i >= NLAYER * tot) return;
    int l = i / tot, r = i - l * tot;
    float v;
    if (r < n1)           v = b1[l*n1 + r];
    else if (r < n1 + n2) v = b2[l*n2 + (r - n1)];
    else                  v = b3[l*n3 + (r - n1 - n2)];
    dst[i] = v;
}

// ---------------------------------------------------------------------------
// Host plumbing
// ---------------------------------------------------------------------------
static inline size_t stage_bytes(int NT) { return (size_t)(2*128*SPITCH + 2*NT*SPITCH) * 2; }

static void gemm(const __nv_bfloat16* Ahp, const __nv_bfloat16* Alp,
                 const __nv_bfloat16* Bhp, const __nv_bfloat16* Blp,
                 float* C, __nv_bfloat16* Ch, __nv_bfloat16* Cl,
                 const float* bias, int M, int N, int K, int lda, int ldb, int ldc,
                 float alpha, int accum, int outmode, int NT,
                 int batches = 1, int bdiv = 1,
                 long long sA1 = 0, long long sA2 = 0,
                 long long sB1 = 0, long long sB2 = 0,
                 long long sC1 = 0, long long sC2 = 0)
{
    dim3 grid((N + NT - 1) / NT, M / 128, batches);
    size_t sm = NSTAGE * stage_bytes(NT);
    if (NT == 256)
        gemm_mma_kernel<256,2,4><<<grid, 256, sm>>>(Ahp, Alp, Bhp, Blp, C, Ch, Cl, bias,
            M, N, K, lda, ldb, ldc, alpha, accum, outmode, bdiv, sA1, sA2, sB1, sB2, sC1, sC2);
    else if (NT == 128)
        gemm_mma_kernel<128,4,2><<<grid, 256, sm>>>(Ahp, Alp, Bhp, Blp, C, Ch, Cl, bias,
            M, N, K, lda, ldb, ldc, alpha, accum, outmode, bdiv, sA1, sA2, sB1, sB2, sC1, sC2);
    else
        gemm_mma_kernel<64,4,2><<<grid, 256, sm>>>(Ahp, Alp, Bhp, Blp, C, Ch, Cl, bias,
            M, N, K, lda, ldb, ldc, alpha, accum, outmode, bdiv, sA1, sA2, sB1, sB2, sC1, sC2);
}

#define SYM(p, s) cudaGetSymbolAddress((void**)&p, s)

extern "C" void kernel_launch(void* const* d_in, const int* in_sizes, int n_in,
                              void* d_out, int out_size)
{
    const float* x       = (const float*)d_in[0];
    const float* in_w    = (const float*)d_in[1];
    const float* in_b    = (const float*)d_in[2];
    const float* norm1_w = (const float*)d_in[3];
    const float* norm2_w = (const float*)d_in[4];
    const float* wq      = (const float*)d_in[5];
    const float* bq      = (const float*)d_in[6];
    const float* wk      = (const float*)d_in[7];
    const float* bk      = (const float*)d_in[8];
    const float* wv      = (const float*)d_in[9];
    const float* bv      = (const float*)d_in[10];
    const float* wo      = (const float*)d_in[11];
    const float* bo      = (const float*)d_in[12];
    const float* w1      = (const float*)d_in[13];
    const float* b1      = (const float*)d_in[14];
    const float* w3      = (const float*)d_in[15];
    const float* b3      = (const float*)d_in[16];
    const float* w2      = (const float*)d_in[17];
    const float* b2      = (const float*)d_in[18];
    const float* onorm_w = (const float*)d_in[19];
    const float* out_w   = (const float*)d_in[20];
    const float* out_b   = (const float*)d_in[21];
    float* out = (float*)d_out;

    cudaFuncSetAttribute(gemm_mma_kernel<256,2,4>,
        cudaFuncAttributeMaxDynamicSharedMemorySize, (int)(NSTAGE * stage_bytes(256)));
    cudaFuncSetAttribute(gemm_mma_kernel<128,4,2>,
        cudaFuncAttributeMaxDynamicSharedMemorySize, (int)(NSTAGE * stage_bytes(128)));
    cudaFuncSetAttribute(gemm_mma_kernel<64,4,2>,
        cudaFuncAttributeMaxDynamicSharedMemorySize, (int)(NSTAGE * stage_bytes(64)));

    __nv_bfloat16 *winh,*winl,*wqkvh,*wqkvl,*woh,*wol,*w13h,*w13l,*w2h,*w2l,*outwh,*outwl;
    __nv_bfloat16 *xh,*xl,*gh,*gl,*qh,*ql,*kh,*kl,*vth,*vtl,*oh,*ol,*ph,*pl,*ffh,*ffl;
    float *h,*qkvf,*sc,*ff13,*bqkv,*b13;
    SYM(winh,g_winh); SYM(winl,g_winl);
    SYM(wqkvh,g_wqkvh); SYM(wqkvl,g_wqkvl);
    SYM(woh,g_woh); SYM(wol,g_wol);
    SYM(w13h,g_w13h); SYM(w13l,g_w13l);
    SYM(w2h,g_w2h); SYM(w2l,g_w2l);
    SYM(outwh,g_outwh); SYM(outwl,g_outwl);
    SYM(xh,g_xh); SYM(xl,g_xl); SYM(gh,g_gh); SYM(gl,g_gl);
    SYM(qh,g_qh); SYM(ql,g_ql); SYM(kh,g_kh); SYM(kl,g_kl);
    SYM(vth,g_vth); SYM(vtl,g_vtl); SYM(oh,g_oh); SYM(ol,g_ol);
    SYM(ph,g_ph); SYM(pl,g_pl); SYM(ffh,g_ffh); SYM(ffl,g_ffl);
    SYM(h,g_h); SYM(qkvf,g_qkvf); SYM(sc,g_sc); SYM(ff13,g_ff13);
    SYM(bqkv,g_bqkv); SYM(b13,g_b13);

    const long long HH  = (long long)HID*HID;
    const long long HA  = (long long)HID*AHID;
    const long long QKV = (long long)3072*HID;   // per-layer fused qkv weight plane
    const long long F13 = (long long)5460*HID;   // per-layer fused ff13 weight plane

    // ---- one-time converters ----
    rope_cache_kernel<<<(SEQ*32 + 255)/256, 256>>>();
    split_kernel<<<(1048576 + 255)/256, 256>>>(x, xh, xl, 1048576);
    concat_bias_kernel<<<(NLAYER*3072 + 255)/256, 256>>>(bq, bk, bv, bqkv, HID, HID, HID);
    concat_bias_kernel<<<(NLAYER*5460 + 255)/256, 256>>>(b1, b3, b1, b13, AHID, AHID, 0);
    {
        dim3 b(32, 8);
        transpose_split_kernel<<<dim3(32, 4, 1),  b>>>(in_w,  winh, winl, DIM,  HID, HID, DIM,  0, 0);
        // fused qkv weight: rows [0,1024)=wq^T, [1024,2048)=wk^T, [2048,3072)=wv^T
        transpose_split_kernel<<<dim3(32, 32, 6), b>>>(wq, wqkvh,            wqkvl,            HID, HID, HID, HID, HH, QKV);
        transpose_split_kernel<<<dim3(32, 32, 6), b>>>(wk, wqkvh + 1024*HID, wqkvl + 1024*HID, HID, HID, HID, HID, HH, QKV);
        transpose_split_kernel<<<dim3(32, 32, 6), b>>>(wv, wqkvh + 2048*HID, wqkvl + 2048*HID, HID, HID, HID, HID, HH, QKV);
        transpose_split_kernel<<<dim3(32, 32, 6), b>>>(wo, woh, wol, HID, HID, HID, HID, HH, HH);
        // fused ff13 weight: rows [0,2730)=w1^T, [2730,5460)=w3^T
        transpose_split_kernel<<<dim3(86, 32, 6), b>>>(w1, w13h,             w13l,             HID, AHID, AHID, HID, HA, F13);
        transpose_split_kernel<<<dim3(86, 32, 6), b>>>(w3, w13h + (long long)AHID*HID, w13l + (long long)AHID*HID, HID, AHID, AHID, HID, HA, F13);
        transpose_split_kernel<<<dim3(32, 86, 6), b>>>(w2, w2h, w2l, AHID, HID, HID, APAD, HA, (long long)HID*APAD);
        transpose_split_kernel<<<dim3(4, 32, 1),  b>>>(out_w, outwh, outwl, HID, DIM, DIM, HID, 0, 0);
    }

    // h = x @ in_w + in_b
    gemm(xh, xl, winh, winl, h, nullptr, nullptr, in_b,
         NTOK, HID, DIM, DIM, DIM, HID, 1.0f, 0, 0, 256);

    for (int l = 0; l < NLAYER; l++) {
        rmsnorm_kernel<<<NTOK, 256>>>(h, norm1_w + (long long)l*HID, gh, gl);

        // fused qkv: [NTOK][3072]
        gemm(gh, gl, wqkvh + l*QKV, wqkvl + l*QKV, qkvf, nullptr, nullptr, bqkv + (long long)l*3072,
             NTOK, 3072, HID, HID, HID, 3072, 1.0f, 0, 0, 256);

        rope_apply_kernel<<<(NTOK*NHEAD*32 + 255)/256, 256>>>(qkvf);
        transpose_split_kernel<<<dim3(32, 256, 1), dim3(32,8)>>>(qkvf + 2048, vth, vtl,
                                                                 NTOK, HID, 3072, NTOK, 0, 0);

        // scores = 0.125 * Q K^T  (z = b*NHEAD + head)
        gemm(qh, ql, kh, kl, sc, nullptr, nullptr, nullptr,
             SEQ, SEQ, HEADDIM, HID, HID, SEQ, 0.125f, 0, 0, 256,
             BATCH*NHEAD, NHEAD,
             (long long)SEQ*HID, HEADDIM,
             (long long)SEQ*HID, HEADDIM,
             (long long)NHEAD*SEQ*SEQ, (long long)SEQ*SEQ);

        softmax_kernel<<<BATCH*NHEAD*SEQ/8, 256>>>(sc, ph, pl);

        // o = P @ V  (bf16 hi/lo planes out)
        gemm(ph, pl, vth, vtl, nullptr, oh, ol, nullptr,
             SEQ, HEADDIM, SEQ, SEQ, NTOK, HID, 1.0f, 0, 1, 64,
             BATCH*NHEAD, NHEAD,
             (long long)NHEAD*SEQ*SEQ, (long long)SEQ*SEQ,
             (long long)SEQ, (long long)HEADDIM*NTOK,
             (long long)SEQ*HID, (long long)HEADDIM);

        // h += (o @ wo + bo) * RS
        gemm(oh, ol, woh + l*HH, wol + l*HH, h, nullptr, nullptr, bo + (long long)l*HID,
             NTOK, HID, HID, HID, HID, HID, RSCALE, 1, 0, 256);

        rmsnorm_kernel<<<NTOK, 256>>>(h, norm2_w + (long long)l*HID, gh, gl);

        // fused ff13: [NTOK][5460] (pitch FPAD)
        gemm(gh, gl, w13h + l*F13, w13l + l*F13, ff13, nullptr, nullptr, b13 + (long long)l*5460,
             NTOK, 5460, HID, HID, HID, FPAD, 1.0f, 0, 0, 256);

        {
            long long n = (long long)NTOK * AHID;
            swiglu_kernel<<<(unsigned)((n + 255) / 256), 256>>>(ff13, ffh, ffl);
        }

        // h += (ffg @ w2 + b2) * RS
        gemm(ffh, ffl, w2h + (long long)l*HID*APAD, w2l + (long long)l*HID*APAD, h,
             nullptr, nullptr, b2 + (long long)l*HID,
             NTOK, HID, AHID, APAD, APAD, HID, RSCALE, 1, 0, 256);
    }

    rmsnorm_kernel<<<NTOK, 256>>>(h, onorm_w, gh, gl);
    gemm(gh, gl, outwh, outwl, out, nullptr, nullptr, out_b,
         NTOK, DIM, HID, HID, HID, DIM, 1.0f, 0, 0, 128);
}